// round 14
// baseline (speedup 1.0000x reference)
#include <cuda_runtime.h>
#include <cuda_fp16.h>
#include <cstdint>
#include <math.h>

// ---------------------------------------------------------------------------
// RWKV forward. GEMMs: mma.sync fp16, single-product (W_in 2-product).
// B-side (weights) read DIRECTLY as fp32 + converted in the load stage
// (no per-replay weight conversion pass). A-side fp16 via cp.async.
// kr/ffk+ffr fused wide GEMMs (two B pointers + column split).
// WKV fused (32 chunks x 32 steps, fp16 IO). LN warp-per-row.
// ---------------------------------------------------------------------------

#define E_DIM   1024
#define FOUR_E  4096
#define D_IN    512
#define BTOK    4096
#define T_LEN   1024
#define BATCH   4
#define NLAYER  11
#define NCH2    32
#define CLEN2   32

#define EE_  1048576ull          // E*E
#define FE_  4194304ull          // 4E*E

// ---------------- device-global scratch (no allocation allowed) ------------
__device__ __half g_inh[BTOK * D_IN],   g_inl[BTOK * D_IN];
__device__ __half g_xnh[BTOK * E_DIM];
__device__ __half g_hbh[BTOK * FOUR_E];
__device__ __half g_yh [BTOK * E_DIM];
__device__ __half g_krh[BTOK * 2 * E_DIM];
__device__ __half g_rh [BTOK * E_DIM];

__device__ float g_res[BTOK * E_DIM];
__device__ float g_tmp[BTOK * E_DIM];

// ---------------------------------------------------------------------------
// helpers
// ---------------------------------------------------------------------------
__device__ __forceinline__ uint32_t smem_u32(const void* p) {
    uint32_t a;
    asm("{ .reg .u64 t; cvta.to.shared.u64 t, %1; cvt.u32.u64 %0, t; }" : "=r"(a) : "l"(p));
    return a;
}
__device__ __forceinline__ void ldm_x4(uint32_t* r, uint32_t addr) {
    asm volatile("ldmatrix.sync.aligned.m8n8.x4.shared.b16 {%0,%1,%2,%3}, [%4];"
        : "=r"(r[0]), "=r"(r[1]), "=r"(r[2]), "=r"(r[3]) : "r"(addr));
}
__device__ __forceinline__ void mma_f16(float* d, const uint32_t* a, uint32_t b0, uint32_t b1) {
    asm volatile("mma.sync.aligned.m16n8k16.row.col.f32.f16.f16.f32 "
        "{%0,%1,%2,%3}, {%4,%5,%6,%7}, {%8,%9}, {%0,%1,%2,%3};"
        : "+f"(d[0]), "+f"(d[1]), "+f"(d[2]), "+f"(d[3])
        : "r"(a[0]), "r"(a[1]), "r"(a[2]), "r"(a[3]), "r"(b0), "r"(b1));
}
__device__ __forceinline__ void cp16(uint32_t s, const void* g) {
    asm volatile("cp.async.cg.shared.global [%0], [%1], 16;" :: "r"(s), "l"(g));
}
__device__ __forceinline__ void cp_commit() {
    asm volatile("cp.async.commit_group;" ::: "memory");
}
template <int N> __device__ __forceinline__ void cp_wait() {
    asm volatile("cp.async.wait_group %0;" :: "n"(N) : "memory");
}
__device__ __forceinline__ void splith2(float2 v, uint32_t& h, uint32_t& l) {
    __half2 hh = __floats2half2_rn(v.x, v.y);
    h = *reinterpret_cast<uint32_t*>(&hh);
    float2 b = __half22float2(hh);
    __half2 ll = __floats2half2_rn(v.x - b.x, v.y - b.y);
    l = *reinterpret_cast<uint32_t*>(&ll);
}
__device__ __forceinline__ uint32_t h2pack(float a, float b) {
    __half2 h = __floats2half2_rn(a, b);
    return *reinterpret_cast<uint32_t*>(&h);
}

// ---------------------------------------------------------------------------
// input conversion: fp32 -> fp16 h/l pair (GEMM A-side for W_in GEMM)
// ---------------------------------------------------------------------------
__global__ void convert_pair(const float4* __restrict__ src,
                             uint2* __restrict__ h, uint2* __restrict__ l, int n4)
{
    const int stride = gridDim.x * blockDim.x;
    for (int i = blockIdx.x * blockDim.x + threadIdx.x; i < n4; i += stride) {
        float4 v = src[i];
        uint2 hh, ll;
        splith2(make_float2(v.x, v.y), hh.x, ll.x);
        splith2(make_float2(v.z, v.w), hh.y, ll.y);
        h[i] = hh;
        l[i] = ll;
    }
}

// ---------------------------------------------------------------------------
// GEMM: C[M,N] = A[M,K] @ W[N,K]^T. A = fp16 (h, optional l) via cp.async.
// B = fp32 source (B1 for cols < BSplit, else B2), register-staged + converted
// to fp16 in smem each stage. CTA 128x128x32, 256 threads (8 warps: 4m x 2n),
// warp tile 32x64, 3 smem stages, 2 CTAs/SM.
// ---------------------------------------------------------------------------
#define TM 128
#define TN 128
#define TK 32
#define GT 256
#define STAGES 3
#define ROWB 80
#define PARTB (128 * ROWB)       // 10240

#define EPI_KR     0             // write fp16, stride N
#define EPI_BIAS   1
#define EPI_FF     2
#define EPI_ADD    3
#define EPI_CMIX   4

#define SMEM_NP2 (STAGES * 3 * PARTB)   // 92160
#define SMEM_NP1 (STAGES * 2 * PARTB)   // 61440

template <int EPI, int NPROD>
__global__ __launch_bounds__(GT, 2)
void gemm_f16(const __half* __restrict__ Ah, const __half* __restrict__ Al,
              const float* __restrict__ B1, const float* __restrict__ B2, int BSplit,
              float* __restrict__ C, int M, int N, int K,
              const float* __restrict__ bias,
              const float* __restrict__ Cin,
              const __half* __restrict__ Rg,
              __half* __restrict__ Oh, __half* __restrict__ Or, int NSplit)
{
    constexpr int STAGE_SZ = (NPROD + 1) * PARTB;
    constexpr int OFF_AL = PARTB;                 // valid when NPROD==2
    constexpr int OFF_B  = NPROD * PARTB;

    extern __shared__ char smem[];
    const uint32_t sbase = smem_u32(smem);
    const int tid  = threadIdx.x;
    const int lane = tid & 31;
    const int wid  = tid >> 5;
    const int wm   = wid & 3;
    const int wn   = wid >> 2;
    const int bm   = blockIdx.y * TM;
    const int bn   = blockIdx.x * TN;

    const int lrow  = lane & 15;
    const int lchun = lane >> 4;

    // B source for this CTA's 128-column block (block never straddles BSplit)
    const float* Bp = (bn < BSplit) ? (B1 + (size_t)bn * K)
                                    : (B2 + (size_t)(bn - BSplit) * K);

    // per-thread B slots: 2 segments of 8 values at (row, seg)
    const int b_row0 = (tid + 0)   >> 2, b_seg0 = (tid + 0)   & 3;
    const int b_row1 = (tid + GT)  >> 2, b_seg1 = (tid + GT)  & 3;

    float4 breg[4];   // 2 segments x 8 floats

    auto ldgB = [&](int s) {
        const int k0 = s * TK;
        const float4* p0 = reinterpret_cast<const float4*>(Bp + (size_t)b_row0 * K + k0 + b_seg0 * 8);
        const float4* p1 = reinterpret_cast<const float4*>(Bp + (size_t)b_row1 * K + k0 + b_seg1 * 8);
        breg[0] = p0[0]; breg[1] = p0[1];
        breg[2] = p1[0]; breg[3] = p1[1];
    };
    auto stsB = [&](int buf) {
        const uint32_t sb = sbase + buf * STAGE_SZ + OFF_B;
        uint4 o0, o1;
        o0.x = h2pack(breg[0].x, breg[0].y); o0.y = h2pack(breg[0].z, breg[0].w);
        o0.z = h2pack(breg[1].x, breg[1].y); o0.w = h2pack(breg[1].z, breg[1].w);
        o1.x = h2pack(breg[2].x, breg[2].y); o1.y = h2pack(breg[2].z, breg[2].w);
        o1.z = h2pack(breg[3].x, breg[3].y); o1.w = h2pack(breg[3].z, breg[3].w);
        *reinterpret_cast<uint4*>(smem + (buf * STAGE_SZ + OFF_B) + b_row0 * ROWB + b_seg0 * 16) = o0;
        *reinterpret_cast<uint4*>(smem + (buf * STAGE_SZ + OFF_B) + b_row1 * ROWB + b_seg1 * 16) = o1;
        (void)sb;
    };
    auto issueA = [&](int s, int buf) {
        const uint32_t sb = sbase + buf * STAGE_SZ;
        const int k0 = s * TK;
#pragma unroll
        for (int i = 0; i < 2; i++) {
            int idx = tid + i * GT;
            int row = idx >> 2, seg = idx & 3;
            uint32_t sa = sb + row * ROWB + seg * 16;
            size_t go = (size_t)(bm + row) * K + k0 + seg * 8;
            cp16(sa, Ah + go);
            if (NPROD == 2) cp16(sa + OFF_AL, Al + go);
        }
        cp_commit();
    };

    float acc[2][8][4];
#pragma unroll
    for (int i = 0; i < 2; i++)
#pragma unroll
        for (int j = 0; j < 8; j++)
#pragma unroll
            for (int q = 0; q < 4; q++) acc[i][j][q] = 0.f;

    const int S = K / TK;

    // prologue: B0 staged to smem now; B1 held in regs until end of iter 0
    ldgB(0); stsB(0);
    issueA(0, 0);
    if (S > 1) ldgB(1);
    if (S > 1) issueA(1, 1);

    for (int s = 0; s < S; s++) {
        const int buf = s % STAGES;
        if (s == S - 1) cp_wait<0>(); else cp_wait<1>();
        __syncthreads();

        const uint32_t sb = sbase + buf * STAGE_SZ;
#pragma unroll
        for (int kk = 0; kk < 2; kk++) {
            const uint32_t koff = (uint32_t)((kk * 2 + lchun) * 16);
            uint32_t ah[2][4], al[2][4];
#pragma unroll
            for (int mt = 0; mt < 2; mt++) {
                uint32_t aa = sb + (uint32_t)((wm * 32 + mt * 16 + lrow) * ROWB) + koff;
                ldm_x4(ah[mt], aa);
                if (NPROD == 2) ldm_x4(al[mt], aa + OFF_AL);
            }
#pragma unroll
            for (int bg = 0; bg < 2; bg++) {
                uint32_t bh[2][4];
#pragma unroll
                for (int bt = 0; bt < 2; bt++) {
                    uint32_t ba = sb + OFF_B +
                        (uint32_t)((wn * 64 + (bg * 2 + bt) * 16 + lrow) * ROWB) + koff;
                    ldm_x4(bh[bt], ba);
                }
#pragma unroll
                for (int mt = 0; mt < 2; mt++)
#pragma unroll
                    for (int bt = 0; bt < 2; bt++)
#pragma unroll
                        for (int j = 0; j < 2; j++)
                            mma_f16(acc[mt][bg * 4 + bt * 2 + j], ah[mt], bh[bt][j], bh[bt][2 + j]);
                if (NPROD == 2) {
#pragma unroll
                    for (int mt = 0; mt < 2; mt++)
#pragma unroll
                        for (int bt = 0; bt < 2; bt++)
#pragma unroll
                            for (int j = 0; j < 2; j++)
                                mma_f16(acc[mt][bg * 4 + bt * 2 + j], al[mt], bh[bt][j], bh[bt][2 + j]);
                }
            }
        }
        // stage s+1's B (in regs since iter s-1 / prologue) -> smem
        if (s + 1 < S) stsB((s + 1) % STAGES);
        // prefetch stage s+2
        if (s + 2 < S) { ldgB(s + 2); issueA(s + 2, (s + 2) % STAGES); }
    }

    // epilogue
#pragma unroll
    for (int mt = 0; mt < 2; mt++)
#pragma unroll
        for (int nt = 0; nt < 8; nt++) {
            const int row0 = bm + wm * 32 + mt * 16 + (lane >> 2);
            const int col  = bn + wn * 64 + (nt >> 1) * 16 + (nt & 1) * 8 + (lane & 3) * 2;
#pragma unroll
            for (int h = 0; h < 2; h++) {
                const int r = row0 + h * 8;
                float2 v = make_float2(acc[mt][nt][2 * h + 0], acc[mt][nt][2 * h + 1]);
                if (EPI == EPI_KR) {
                    *reinterpret_cast<uint32_t*>(Oh + (size_t)r * N + col) = h2pack(v.x, v.y);
                }
                if (EPI == EPI_BIAS) {
                    float2 bb = *reinterpret_cast<const float2*>(bias + col);
                    v.x += bb.x; v.y += bb.y;
                    *reinterpret_cast<float2*>(C + (size_t)r * N + col) = v;
                }
                if (EPI == EPI_FF) {
                    if (col < NSplit) {
                        v.x = v.x > 0.f ? v.x * v.x : 0.f;
                        v.y = v.y > 0.f ? v.y * v.y : 0.f;
                        *reinterpret_cast<uint32_t*>(Oh + (size_t)r * NSplit + col) =
                            h2pack(v.x, v.y);
                    } else {
                        *reinterpret_cast<uint32_t*>(Or + (size_t)r * (N - NSplit) + col - NSplit) =
                            h2pack(v.x, v.y);
                    }
                }
                if (EPI == EPI_ADD) {
                    const size_t idx = (size_t)r * N + col;
                    float2 ci = *reinterpret_cast<const float2*>(Cin + idx);
                    v.x += ci.x; v.y += ci.y;
                    *reinterpret_cast<float2*>(C + idx) = v;
                }
                if (EPI == EPI_CMIX) {
                    const size_t idx = (size_t)r * N + col;
                    float2 ci = *reinterpret_cast<const float2*>(Cin + idx);
                    uint32_t rp = *reinterpret_cast<const uint32_t*>(Rg + idx);
                    float2 rr = __half22float2(*reinterpret_cast<const __half2*>(&rp));
                    v.x = ci.x + v.x * (1.f / (1.f + __expf(-rr.x)));
                    v.y = ci.y + v.y * (1.f / (1.f + __expf(-rr.y)));
                    *reinterpret_cast<float2*>(C + idx) = v;
                }
            }
        }
}

// ---------------------------------------------------------------------------
// LayerNorm over E=1024, warp-per-row: 256 threads = 8 warps = 8 rows/CTA.
// ---------------------------------------------------------------------------
__global__ __launch_bounds__(256)
void ln_kernel(const float* __restrict__ x, float* __restrict__ o,
               __half* __restrict__ oh,
               const float* __restrict__ g, const float* __restrict__ b)
{
    const int lane = threadIdx.x & 31;
    const int row  = blockIdx.x * 8 + (threadIdx.x >> 5);

    const float4* xr = reinterpret_cast<const float4*>(x + (size_t)row * E_DIM);
    float4 v[8];
    float s = 0.f, ss = 0.f;
#pragma unroll
    for (int i = 0; i < 8; i++) {
        v[i] = xr[lane + i * 32];
        s  += v[i].x + v[i].y + v[i].z + v[i].w;
        ss += v[i].x * v[i].x + v[i].y * v[i].y + v[i].z * v[i].z + v[i].w * v[i].w;
    }
#pragma unroll
    for (int off = 16; off > 0; off >>= 1) {
        s  += __shfl_xor_sync(0xffffffffu, s, off);
        ss += __shfl_xor_sync(0xffffffffu, ss, off);
    }
    const float mean = s * (1.f / E_DIM);
    const float inv  = rsqrtf(ss * (1.f / E_DIM) - mean * mean + 1e-5f);

#pragma unroll
    for (int i = 0; i < 8; i++) {
        const int c = lane + i * 32;
        float4 gg = reinterpret_cast<const float4*>(g)[c];
        float4 bb = reinterpret_cast<const float4*>(b)[c];
        float4 ov;
        ov.x = (v[i].x - mean) * inv * gg.x + bb.x;
        ov.y = (v[i].y - mean) * inv * gg.y + bb.y;
        ov.z = (v[i].z - mean) * inv * gg.z + bb.z;
        ov.w = (v[i].w - mean) * inv * gg.w + bb.w;
        if (o) reinterpret_cast<float4*>(o + (size_t)row * E_DIM)[c] = ov;
        if (oh) {
            uint2 hh;
            hh.x = h2pack(ov.x, ov.y);
            hh.y = h2pack(ov.z, ov.w);
            reinterpret_cast<uint2*>(oh + (size_t)row * E_DIM)[c] = hh;
        }
    }
}

// ---------------------------------------------------------------------------
// WKV recurrence, fused single kernel. Block = 1024 threads = 32 channels x
// 32 chunks of 32 steps; chunk states in smem; warp-uniform prefix; fp16 IO.
// kr layout: k at col e, v==r at col 1024+e, row stride 2048 (fp16).
// ---------------------------------------------------------------------------
__global__ __launch_bounds__(1024)
void wkv_fused(const __half* __restrict__ kr,
               const float* __restrict__ decay, const float* __restrict__ first,
               __half* __restrict__ yh)
{
    __shared__ float s_a[NCH2][32], s_b[NCH2][32], s_p[NCH2][32];
    const int ch = threadIdx.x & 31;
    const int c  = threadIdx.x >> 5;          // chunk, warp-uniform
    const int e  = blockIdx.x * 32 + ch;
    const int b  = blockIdx.y;
    const float w = -__expf(decay[e]);
    const float u = first[e];

    const size_t base  = ((size_t)b * T_LEN + (size_t)c * CLEN2) * 2048 + e;
    const size_t ybase = ((size_t)b * T_LEN + (size_t)c * CLEN2) * E_DIM + e;
    const __half* kp = kr + base;

    // pass 1: chunk-local scan from zero state
    float aa = 0.f, bb = 0.f, pp = -1e38f;
#pragma unroll 4
    for (int t = 0; t < CLEN2; t++) {
        float kt = __half2float(kp[(size_t)t * 2048]);
        float vt = __half2float(kp[(size_t)t * 2048 + 1024]);
        float ww = pp + w;
        float p  = fmaxf(ww, kt);
        float e1 = __expf(ww - p), e2 = __expf(kt - p);
        aa = e1 * aa + e2 * vt;
        bb = e1 * bb + e2;
        pp = p;
    }
    s_a[c][ch] = aa; s_b[c][ch] = bb; s_p[c][ch] = pp;
    __syncthreads();

    // prefix over previous chunks (<=31 iters, warp-uniform trip count)
    aa = 0.f; bb = 0.f; pp = -1e38f;
    for (int j = 0; j < c; j++) {
        float pd = pp + (float)CLEN2 * w;
        float a2 = s_a[j][ch], b2 = s_b[j][ch], p2 = s_p[j][ch];
        float p  = fmaxf(pd, p2);
        float e1 = __expf(pd - p), e2 = __expf(p2 - p);
        aa = e1 * aa + e2 * a2;
        bb = e1 * bb + e2 * b2;
        pp = p;
    }

    // replay emitting y = sigmoid(r) * wkv  (v == r)
    for (int t = 0; t < CLEN2; t++) {
        float kt = __half2float(kp[(size_t)t * 2048]);
        float vt = __half2float(kp[(size_t)t * 2048 + 1024]);
        float ww = u + kt;
        float p  = fmaxf(pp, ww);
        float e1 = __expf(pp - p), e2 = __expf(ww - p);
        float yt = (e1 * aa + e2 * vt) / (e1 * bb + e2);
        float ys = yt * (1.f / (1.f + __expf(-vt)));
        yh[ybase + (size_t)t * E_DIM] = __float2half_rn(ys);
        float ww2 = pp + w;
        float p2  = fmaxf(ww2, kt);
        e1 = __expf(ww2 - p2); e2 = __expf(kt - p2);
        aa = e1 * aa + e2 * vt;
        bb = e1 * bb + e2;
        pp = p2;
    }
}

// ---------------------------------------------------------------------------
// Host orchestration
// ---------------------------------------------------------------------------
static void set_smem_attrs() {
    cudaFuncSetAttribute(gemm_f16<EPI_BIAS, 2>, cudaFuncAttributeMaxDynamicSharedMemorySize, SMEM_NP2);
    cudaFuncSetAttribute(gemm_f16<EPI_KR,   1>, cudaFuncAttributeMaxDynamicSharedMemorySize, SMEM_NP1);
    cudaFuncSetAttribute(gemm_f16<EPI_FF,   1>, cudaFuncAttributeMaxDynamicSharedMemorySize, SMEM_NP1);
    cudaFuncSetAttribute(gemm_f16<EPI_ADD,  1>, cudaFuncAttributeMaxDynamicSharedMemorySize, SMEM_NP1);
    cudaFuncSetAttribute(gemm_f16<EPI_CMIX, 1>, cudaFuncAttributeMaxDynamicSharedMemorySize, SMEM_NP1);
}

#define NOSPLIT 0x40000000

extern "C" void kernel_launch(void* const* d_in, const int* in_sizes, int n_in,
                              void* d_out, int out_size)
{
    const float* inp    = (const float*)d_in[0];
    const float* W_in   = (const float*)d_in[1];
    const float* b_in   = (const float*)d_in[2];
    const float* ln0g   = (const float*)d_in[3];
    const float* ln0b   = (const float*)d_in[4];
    const float* l0ln1g = (const float*)d_in[5];
    const float* l0ln1b = (const float*)d_in[6];
    const float* l0ln2g = (const float*)d_in[7];
    const float* l0ln2b = (const float*)d_in[8];
    const float* l0cmk  = (const float*)d_in[9];
    const float* l0cmv  = (const float*)d_in[10];
    const float* l0cmr  = (const float*)d_in[11];
    const float* l0ffk  = (const float*)d_in[12];
    const float* l0ffv  = (const float*)d_in[13];
    const float* l0ffr  = (const float*)d_in[14];
    const float* tmk    = (const float*)d_in[15];
    const float* tmr    = (const float*)d_in[16];
    const float* tmo    = (const float*)d_in[17];
    const float* tmdec  = (const float*)d_in[18];
    const float* tmfst  = (const float*)d_in[19];
    const float* ln1g   = (const float*)d_in[20];
    const float* ln1b   = (const float*)d_in[21];
    const float* ln2g   = (const float*)d_in[22];
    const float* ln2b   = (const float*)d_in[23];
    const float* ffk    = (const float*)d_in[24];
    const float* ffv    = (const float*)d_in[25];
    const float* ffr    = (const float*)d_in[26];
    const float* outg   = (const float*)d_in[27];
    const float* outb   = (const float*)d_in[28];
    float* out = (float*)d_out;

    set_smem_attrs();

    __half *inh, *inl, *xnh, *hbh, *yh, *krh, *rh;
    float *res, *tmp;
    cudaGetSymbolAddress((void**)&inh, g_inh);
    cudaGetSymbolAddress((void**)&inl, g_inl);
    cudaGetSymbolAddress((void**)&xnh, g_xnh);
    cudaGetSymbolAddress((void**)&hbh, g_hbh);
    cudaGetSymbolAddress((void**)&yh,  g_yh);
    cudaGetSymbolAddress((void**)&krh, g_krh);
    cudaGetSymbolAddress((void**)&rh,  g_rh);
    cudaGetSymbolAddress((void**)&res, g_res);
    cudaGetSymbolAddress((void**)&tmp, g_tmp);

    convert_pair<<<1024, 256>>>((const float4*)inp, (uint2*)inh, (uint2*)inl,
                                (int)((size_t)BTOK * D_IN / 4));

    const dim3 gE   (E_DIM / TN,  BTOK / TM);   // (8, 32)
    const dim3 gKR  (2048 / TN,   BTOK / TM);   // (16, 32)
    const dim3 gFF  (5120 / TN,   BTOK / TM);   // (40, 32)
    const dim3 gWKV (E_DIM / 32,  BATCH);       // (32, 4) x 1024 thr
    const int  gLN  = BTOK / 8;                 // 512 CTAs, warp-per-row

    // x = inputs @ W_in^T + b_in ; res = LN(x, ln0)
    gemm_f16<EPI_BIAS, 2><<<gE, GT, SMEM_NP2>>>(inh, inl, W_in, nullptr, NOSPLIT,
        tmp, BTOK, E_DIM, D_IN, b_in, nullptr, nullptr, nullptr, nullptr, 0);
    ln_kernel<<<gLN, 256>>>(tmp, res, nullptr, ln0g, ln0b);

    // channel mix (fused ffk+ffr GEMM 1-prod, ffv GEMM 1-prod, fp16 r gate)
    auto cmix = [&](const float* lg, const float* lb,
                    const float* Wk, const float* Wr, const float* Wv) {
        ln_kernel<<<gLN, 256>>>(res, nullptr, xnh, lg, lb);
        gemm_f16<EPI_FF, 1><<<gFF, GT, SMEM_NP1>>>(xnh, nullptr, Wk, Wr, FOUR_E,
            nullptr, BTOK, 5120, E_DIM, nullptr, nullptr, nullptr, hbh, rh, FOUR_E);
        gemm_f16<EPI_CMIX, 1><<<gE, GT, SMEM_NP1>>>(hbh, nullptr, Wv, nullptr, NOSPLIT,
            res, BTOK, E_DIM, FOUR_E, nullptr, res, rh, nullptr, nullptr, 0);
    };

    cmix(l0ln1g, l0ln1b, l0cmk, l0cmr, l0cmv);
    cmix(l0ln2g, l0ln2b, l0ffk, l0ffr, l0ffv);

    for (int l = 0; l < NLAYER; l++) {
        const size_t oE = (size_t)l * E_DIM;

        ln_kernel<<<gLN, 256>>>(res, nullptr, xnh, ln1g + oE, ln1b + oE);
        gemm_f16<EPI_KR, 1><<<gKR, GT, SMEM_NP1>>>(xnh, nullptr,
            tmk + (size_t)l * EE_, tmr + (size_t)l * EE_, E_DIM,
            nullptr, BTOK, 2048, E_DIM, nullptr, nullptr, nullptr, krh, nullptr, 0);
        wkv_fused<<<gWKV, 1024>>>(krh, tmdec + oE, tmfst + oE, yh);
        gemm_f16<EPI_ADD, 1><<<gE, GT, SMEM_NP1>>>(yh, nullptr,
            tmo + (size_t)l * EE_, nullptr, NOSPLIT,
            res, BTOK, E_DIM, E_DIM, nullptr, res, nullptr, nullptr, nullptr, 0);

        ln_kernel<<<gLN, 256>>>(res, nullptr, xnh, ln2g + oE, ln2b + oE);
        gemm_f16<EPI_FF, 1><<<gFF, GT, SMEM_NP1>>>(xnh, nullptr,
            ffk + (size_t)l * FE_, ffr + (size_t)l * EE_, FOUR_E,
            nullptr, BTOK, 5120, E_DIM, nullptr, nullptr, nullptr, hbh, rh, FOUR_E);
        gemm_f16<EPI_CMIX, 1><<<gE, GT, SMEM_NP1>>>(hbh, nullptr,
            ffv + (size_t)l * FE_, nullptr, NOSPLIT,
            res, BTOK, E_DIM, FOUR_E, nullptr, res, rh, nullptr, nullptr, 0);
    }

    ln_kernel<<<gLN, 256>>>(res, out, nullptr, outg, outb);
}